// round 14
// baseline (speedup 1.0000x reference)
#include <cuda_runtime.h>
#include <cuda_fp16.h>
#include <cstdint>
#include <cstddef>

// ============================================================
// Problem constants
// ============================================================
#define TOKENS 32768
#define HIDDEN 2048
#define EPSV   1e-6f

// GEMM tiling (exact R5 configuration — best known: 565us/GEMM)
constexpr int TM  = 128;            // CTA M tile
constexpr int TN  = 256;            // CTA N tile
constexpr int TK  = 64;             // K chunk (fp16 -> 128 bytes/row = SW128 atom)
constexpr int KCH = HIDDEN / TK;    // 32 chunks

constexpr int ST_A = TM * 128;          // 16384 B per A subtile (hi or lo)
constexpr int ST_B = TN * 128;          // 32768 B for B
constexpr int STAGE_BYTES = 2 * ST_A + ST_B;       // 65536
constexpr int SMEM_TILES  = 1024;
constexpr int SMEM_TOTAL  = SMEM_TILES + 2 * STAGE_BYTES;  // 132096

// ============================================================
// Device scratch (no allocation allowed)
// ============================================================
__device__ float   g_resid[(size_t)TOKENS * HIDDEN];
__device__ __half  g_yhi  [(size_t)TOKENS * HIDDEN];
__device__ __half  g_ylo  [(size_t)TOKENS * HIDDEN];
__device__ __half  g_whT  [3][(size_t)HIDDEN * HIDDEN];   // W^T fp16

// ============================================================
// Helpers
// ============================================================
__device__ __forceinline__ uint32_t smem_u32(const void* p) {
    uint32_t a;
    asm("{ .reg .u64 t; cvta.to.shared.u64 t, %1; cvt.u32.u64 %0, t; }" : "=r"(a) : "l"(p));
    return a;
}

#define SW128(o) ((o) ^ (((o) >> 3) & 0x70))

#define CP_ASYNC16(dst, src) \
    asm volatile("cp.async.cg.shared.global [%0], [%1], 16;\n" :: "r"(dst), "l"(src))
#define CP_COMMIT() asm volatile("cp.async.commit_group;\n" ::: "memory")
#define CP_WAIT1()  asm volatile("cp.async.wait_group 1;\n" ::: "memory")
#define CP_WAIT0()  asm volatile("cp.async.wait_group 0;\n" ::: "memory")

__device__ __forceinline__ void ldsm_x4(uint32_t addr, uint32_t& r0, uint32_t& r1,
                                        uint32_t& r2, uint32_t& r3) {
    asm volatile("ldmatrix.sync.aligned.m8n8.x4.shared.b16 {%0,%1,%2,%3}, [%4];"
        : "=r"(r0), "=r"(r1), "=r"(r2), "=r"(r3) : "r"(addr));
}
__device__ __forceinline__ void ldsm_x2(uint32_t addr, uint32_t& r0, uint32_t& r1) {
    asm volatile("ldmatrix.sync.aligned.m8n8.x2.shared.b16 {%0,%1}, [%2];"
        : "=r"(r0), "=r"(r1) : "r"(addr));
}
__device__ __forceinline__ void mma16816(float& d0, float& d1, float& d2, float& d3,
                                         uint32_t a0, uint32_t a1, uint32_t a2, uint32_t a3,
                                         uint32_t b0, uint32_t b1) {
    asm volatile(
        "mma.sync.aligned.m16n8k16.row.col.f32.f16.f16.f32 "
        "{%0,%1,%2,%3}, {%4,%5,%6,%7}, {%8,%9}, {%0,%1,%2,%3};"
        : "+f"(d0), "+f"(d1), "+f"(d2), "+f"(d3)
        : "r"(a0), "r"(a1), "r"(a2), "r"(a3), "r"(b0), "r"(b1));
}

// ============================================================
// Weight prep: transpose + fp16 round.  W[k][n] -> WT[n][k]
// blockIdx.z selects between the two weight pointers so three matrices
// fit in TWO launches (shifts ncu's skip-index onto a gemm launch).
// ============================================================
__global__ void prep_w(const float* __restrict__ Wa, const float* __restrict__ Wb,
                       int widx0) {
    const float* W = (blockIdx.z == 0) ? Wa : Wb;
    int widx = widx0 + (int)blockIdx.z;
    __shared__ float t[32][33];
    int x = blockIdx.x * 32 + threadIdx.x;   // n
    int y = blockIdx.y * 32 + threadIdx.y;   // k
    t[threadIdx.y][threadIdx.x] = W[(size_t)y * HIDDEN + x];
    __syncthreads();
    int n = blockIdx.x * 32 + threadIdx.y;
    int k = blockIdx.y * 32 + threadIdx.x;
    g_whT[widx][(size_t)n * HIDDEN + k] = __float2half_rn(t[threadIdx.x][threadIdx.y]);
}

// ============================================================
// Fused (relu) + rmsnorm.  flags: bit0 = relu (reads `in`, writes resid),
// bit1 = write split fp16 hi/lo.  Else write fp32 outf.
// ============================================================
__global__ void __launch_bounds__(256) norm_kernel(const float* __restrict__ in,
                                                   const float* __restrict__ gain,
                                                   float* __restrict__ outf,
                                                   int flags) {
    int row = blockIdx.x;
    int tid = threadIdx.x;
    const float* src = in ? in : g_resid;
    const float4* inp = reinterpret_cast<const float4*>(src + (size_t)row * HIDDEN);
    float4 v0 = inp[tid];
    float4 v1 = inp[tid + 256];

    if (flags & 1) {
        v0.x = fmaxf(v0.x, 0.f); v0.y = fmaxf(v0.y, 0.f);
        v0.z = fmaxf(v0.z, 0.f); v0.w = fmaxf(v0.w, 0.f);
        v1.x = fmaxf(v1.x, 0.f); v1.y = fmaxf(v1.y, 0.f);
        v1.z = fmaxf(v1.z, 0.f); v1.w = fmaxf(v1.w, 0.f);
        float4* rr = reinterpret_cast<float4*>(g_resid + (size_t)row * HIDDEN);
        rr[tid] = v0;
        rr[tid + 256] = v1;
    }

    float ss = v0.x * v0.x + v0.y * v0.y + v0.z * v0.z + v0.w * v0.w
             + v1.x * v1.x + v1.y * v1.y + v1.z * v1.z + v1.w * v1.w;
#pragma unroll
    for (int o = 16; o; o >>= 1) ss += __shfl_xor_sync(0xFFFFFFFFu, ss, o);
    __shared__ float red[8];
    if ((tid & 31) == 0) red[tid >> 5] = ss;
    __syncthreads();
    float tot = 0.f;
#pragma unroll
    for (int i = 0; i < 8; i++) tot += red[i];
    float scale = rsqrtf(tot * (1.0f / HIDDEN) + EPSV);

    const float4* gp = reinterpret_cast<const float4*>(gain);
    float4 gv0 = gp[tid], gv1 = gp[tid + 256];
    float4 y0, y1;
    y0.x = v0.x * scale * gv0.x; y0.y = v0.y * scale * gv0.y;
    y0.z = v0.z * scale * gv0.z; y0.w = v0.w * scale * gv0.w;
    y1.x = v1.x * scale * gv1.x; y1.y = v1.y * scale * gv1.y;
    y1.z = v1.z * scale * gv1.z; y1.w = v1.w * scale * gv1.w;

    if (flags & 2) {
        float yv[8] = {y0.x, y0.y, y0.z, y0.w, y1.x, y1.y, y1.z, y1.w};
        __half h[8], l[8];
#pragma unroll
        for (int i = 0; i < 8; i++) {
            h[i] = __float2half_rn(yv[i]);
            l[i] = __float2half_rn(yv[i] - __half2float(h[i]));
        }
        uint2* hp = reinterpret_cast<uint2*>(g_yhi + (size_t)row * HIDDEN);
        uint2* lp = reinterpret_cast<uint2*>(g_ylo + (size_t)row * HIDDEN);
        uint2 ph0, ph1, pl0, pl1;
        __half2 t;
        t = __half2(h[0], h[1]); ph0.x = *reinterpret_cast<uint32_t*>(&t);
        t = __half2(h[2], h[3]); ph0.y = *reinterpret_cast<uint32_t*>(&t);
        t = __half2(h[4], h[5]); ph1.x = *reinterpret_cast<uint32_t*>(&t);
        t = __half2(h[6], h[7]); ph1.y = *reinterpret_cast<uint32_t*>(&t);
        t = __half2(l[0], l[1]); pl0.x = *reinterpret_cast<uint32_t*>(&t);
        t = __half2(l[2], l[3]); pl0.y = *reinterpret_cast<uint32_t*>(&t);
        t = __half2(l[4], l[5]); pl1.x = *reinterpret_cast<uint32_t*>(&t);
        t = __half2(l[6], l[7]); pl1.y = *reinterpret_cast<uint32_t*>(&t);
        hp[tid] = ph0; hp[tid + 256] = ph1;
        lp[tid] = pl0; lp[tid + 256] = pl1;
    } else {
        float4* op = reinterpret_cast<float4*>(outf + (size_t)row * HIDDEN);
        op[tid] = y0;
        op[tid + 256] = y1;
    }
}

// ============================================================
// Loader: one K chunk (A hi, A lo, B) into SW128 SMEM stage. 256 threads.
// ============================================================
__device__ __forceinline__ void load_chunk(uint32_t sbase, int m0, int n0, int k0,
                                           const char* Bh, int tid) {
    const char* Ah = reinterpret_cast<const char*>(g_yhi);
    const char* Al = reinterpret_cast<const char*>(g_ylo);
    // A: 2 tensors x 128 rows x 8 x 16B = 2048 transfers
#pragma unroll
    for (int i = tid; i < 2048; i += 256) {
        int t = i >> 10; int rem = i & 1023; int r = rem >> 3; int cb = (rem & 7) * 16;
        uint32_t dst = sbase + t * ST_A + SW128(r * 128 + cb);
        const char* src = (t ? Al : Ah) + ((size_t)(m0 + r) * HIDDEN + k0) * 2 + cb;
        CP_ASYNC16(dst, src);
    }
    // B: 256 rows x 8 x 16B = 2048 transfers
#pragma unroll
    for (int i = tid; i < 2048; i += 256) {
        int r = i >> 3; int cb = (i & 7) * 16;
        uint32_t dst = sbase + 2 * ST_A + SW128(r * 128 + cb);
        const char* src = Bh + ((size_t)(n0 + r) * HIDDEN + k0) * 2 + cb;
        CP_ASYNC16(dst, src);
    }
}

// ============================================================
// GEMM: resid[m,n] += sum_k y[m,k] * W[k,n]  (split fp16 x2 — exact R5 body)
// 2-stage cp.async double buffer, 8 warps (2m x 4n), warp tile 64x64.
// ============================================================
__global__ void __launch_bounds__(256, 1) __cluster_dims__(1, 1, 1)
gemm_kernel(int widx) {
    extern __shared__ char smem[];
    uint32_t sb = smem_u32(smem);
    int tid = threadIdx.x, wid = tid >> 5, lid = tid & 31;
    int n0 = blockIdx.x * TN;
    int m0 = blockIdx.y * TM;
    const char* Bhg = reinterpret_cast<const char*>(g_whT[widx]);

    const uint32_t stage_base[2] = { sb + SMEM_TILES, sb + SMEM_TILES + STAGE_BYTES };

    int wm = wid & 1;
    int wn = wid >> 1;
    int wm0 = wm * 64;
    int wn0 = wn * 64;

    float acc[4][8][4];
#pragma unroll
    for (int i = 0; i < 4; i++)
#pragma unroll
        for (int j = 0; j < 8; j++)
#pragma unroll
            for (int q = 0; q < 4; q++) acc[i][j][q] = 0.f;

    load_chunk(stage_base[0], m0, n0, 0, Bhg, tid);
    CP_COMMIT();

    for (int c = 0; c < KCH; ++c) {
        int s = c & 1;
        if (c + 1 < KCH) {
            load_chunk(stage_base[(c + 1) & 1], m0, n0, (c + 1) * TK, Bhg, tid);
            CP_COMMIT();
            CP_WAIT1();
        } else {
            CP_WAIT0();
        }
        __syncthreads();

        uint32_t aBaseH = stage_base[s];
        uint32_t aBaseL = stage_base[s] + ST_A;
        uint32_t bBaseH = stage_base[s] + 2 * ST_A;

#pragma unroll
        for (int ks = 0; ks < 4; ++ks) {
            int kbyte = ks * 32;   // 16 fp16 per k-step
            uint32_t ah[4][4], al[4][4];
#pragma unroll
            for (int mt = 0; mt < 4; ++mt) {
                int r = wm0 + mt * 16 + (lid & 15);
                int cb = kbyte + ((lid >> 4) << 4);
                uint32_t off = SW128(r * 128 + cb);
                ldsm_x4(aBaseH + off, ah[mt][0], ah[mt][1], ah[mt][2], ah[mt][3]);
                ldsm_x4(aBaseL + off, al[mt][0], al[mt][1], al[mt][2], al[mt][3]);
            }
#pragma unroll
            for (int nt = 0; nt < 8; ++nt) {
                int r = wn0 + nt * 8 + (lid & 7);
                int cb = kbyte + (((lid >> 3) & 1) << 4);
                uint32_t off = SW128(r * 128 + cb);
                uint32_t b0, b1;
                ldsm_x2(bBaseH + off, b0, b1);
#pragma unroll
                for (int mt = 0; mt < 4; ++mt) {
                    mma16816(acc[mt][nt][0], acc[mt][nt][1], acc[mt][nt][2], acc[mt][nt][3],
                             ah[mt][0], ah[mt][1], ah[mt][2], ah[mt][3], b0, b1);
                    mma16816(acc[mt][nt][0], acc[mt][nt][1], acc[mt][nt][2], acc[mt][nt][3],
                             al[mt][0], al[mt][1], al[mt][2], al[mt][3], b0, b1);
                }
            }
        }
        __syncthreads();
    }

    // epilogue: resid += acc
    {
        int qrow = lid >> 2;
        int qcol = (lid & 3) * 2;
#pragma unroll
        for (int mt = 0; mt < 4; ++mt) {
#pragma unroll
            for (int nt = 0; nt < 8; ++nt) {
                int grow = m0 + wm0 + mt * 16 + qrow;
                int gcol = n0 + wn0 + nt * 8 + qcol;
                float* p0 = g_resid + (size_t)grow * HIDDEN + gcol;
                float2 v0 = *reinterpret_cast<float2*>(p0);
                v0.x += acc[mt][nt][0]; v0.y += acc[mt][nt][1];
                *reinterpret_cast<float2*>(p0) = v0;
                float* p1 = g_resid + (size_t)(grow + 8) * HIDDEN + gcol;
                float2 v1 = *reinterpret_cast<float2*>(p1);
                v1.x += acc[mt][nt][2]; v1.y += acc[mt][nt][3];
                *reinterpret_cast<float2*>(p1) = v1;
            }
        }
    }
}

// ============================================================
// kernel_launch
// Launch order: prep(W0), prep(W1,W2), norm, gemm, norm, gemm, norm, gemm, norm
// -> ncu's "-s 5 -c 1" capture lands on the SECOND gemm launch.
// ============================================================
extern "C" void kernel_launch(void* const* d_in, const int* in_sizes, int n_in,
                              void* d_out, int out_size) {
    const float* x  = (const float*)d_in[0];
    const float* g0 = (const float*)d_in[1];
    const float* g1 = (const float*)d_in[2];
    const float* g2 = (const float*)d_in[3];
    const float* g3 = (const float*)d_in[4];
    const float* W[3] = { (const float*)d_in[5], (const float*)d_in[6], (const float*)d_in[7] };
    const float* gains[3] = { g1, g2, g3 };
    float* out = (float*)d_out;

    cudaFuncSetAttribute(gemm_kernel, cudaFuncAttributeMaxDynamicSharedMemorySize, SMEM_TOTAL);

    dim3 pb(32, 32);
    prep_w<<<dim3(HIDDEN / 32, HIDDEN / 32, 1), pb>>>(W[0], W[0], 0);
    prep_w<<<dim3(HIDDEN / 32, HIDDEN / 32, 2), pb>>>(W[1], W[2], 1);

    norm_kernel<<<TOKENS, 256>>>(x, g0, nullptr, /*relu + split*/ 3);

    dim3 gg(HIDDEN / TN, TOKENS / TM);  // (8, 256)
    for (int s = 0; s < 3; s++) {
        gemm_kernel<<<gg, 256, SMEM_TOTAL>>>(s);
        if (s < 2) {
            norm_kernel<<<TOKENS, 256>>>(nullptr, gains[s], nullptr, /*split*/ 2);
        } else {
            norm_kernel<<<TOKENS, 256>>>(nullptr, gains[s], out, /*fp32 out*/ 0);
        }
    }
}

// round 15
// speedup vs baseline: 1.5364x; 1.5364x over previous
#include <cuda_runtime.h>
#include <cuda_fp16.h>
#include <cstdint>
#include <cstddef>

// ============================================================
// Problem constants
// ============================================================
#define TOKENS 32768
#define HIDDEN 2048
#define EPSV   1e-6f

// GEMM tiling
constexpr int TM  = 128;            // CTA M tile
constexpr int TN  = 256;            // CTA N tile
constexpr int TK  = 64;             // K chunk (fp16 -> 128 bytes/row = SW128 atom)
constexpr int KCH = HIDDEN / TK;    // 32 chunks
constexpr int NTHREADS = 256;       // 8 warps: 2(m) x 4(n), warp tile 64x64

constexpr int ST_A = TM * 128;          // 16384 B (A fp16)
constexpr int ST_B = TN * 128;          // 32768 B (B fp16)
constexpr int STAGE_BYTES = ST_A + ST_B;           // 49152
constexpr int NSTAGE = 4;
constexpr int SMEM_TILES  = 1024;
constexpr int SMEM_TOTAL  = SMEM_TILES + NSTAGE * STAGE_BYTES;  // 197632 -> 1 CTA/SM

// ============================================================
// Device scratch (no allocation allowed)
// ============================================================
__device__ float   g_resid[(size_t)TOKENS * HIDDEN];
__device__ __half  g_y    [(size_t)TOKENS * HIDDEN];          // rmsnorm output, fp16
__device__ __half  g_whT  [3][(size_t)HIDDEN * HIDDEN];       // W^T fp16

// ============================================================
// Helpers
// ============================================================
__device__ __forceinline__ uint32_t smem_u32(const void* p) {
    uint32_t a;
    asm("{ .reg .u64 t; cvta.to.shared.u64 t, %1; cvt.u32.u64 %0, t; }" : "=r"(a) : "l"(p));
    return a;
}

#define SW128(o) ((o) ^ (((o) >> 3) & 0x70))

#define CP_ASYNC16(dst, src) \
    asm volatile("cp.async.cg.shared.global [%0], [%1], 16;\n" :: "r"(dst), "l"(src))
#define CP_COMMIT() asm volatile("cp.async.commit_group;\n" ::: "memory")
#define CP_WAIT3()  asm volatile("cp.async.wait_group 3;\n" ::: "memory")
#define CP_WAIT2()  asm volatile("cp.async.wait_group 2;\n" ::: "memory")
#define CP_WAIT1()  asm volatile("cp.async.wait_group 1;\n" ::: "memory")
#define CP_WAIT0()  asm volatile("cp.async.wait_group 0;\n" ::: "memory")

__device__ __forceinline__ void ldsm_x4(uint32_t addr, uint32_t& r0, uint32_t& r1,
                                        uint32_t& r2, uint32_t& r3) {
    asm volatile("ldmatrix.sync.aligned.m8n8.x4.shared.b16 {%0,%1,%2,%3}, [%4];"
        : "=r"(r0), "=r"(r1), "=r"(r2), "=r"(r3) : "r"(addr));
}
__device__ __forceinline__ void mma16816(float& d0, float& d1, float& d2, float& d3,
                                         uint32_t a0, uint32_t a1, uint32_t a2, uint32_t a3,
                                         uint32_t b0, uint32_t b1) {
    asm volatile(
        "mma.sync.aligned.m16n8k16.row.col.f32.f16.f16.f32 "
        "{%0,%1,%2,%3}, {%4,%5,%6,%7}, {%8,%9}, {%0,%1,%2,%3};"
        : "+f"(d0), "+f"(d1), "+f"(d2), "+f"(d3)
        : "r"(a0), "r"(a1), "r"(a2), "r"(a3), "r"(b0), "r"(b1));
}

// ============================================================
// Weight prep: transpose + fp16 round.  W[k][n] -> WT[n][k]
// blockIdx.z selects between the two weight pointers so three matrices
// fit in TWO launches (keeps ncu's skip-index on a gemm launch).
// ============================================================
__global__ void prep_w(const float* __restrict__ Wa, const float* __restrict__ Wb,
                       int widx0) {
    const float* W = (blockIdx.z == 0) ? Wa : Wb;
    int widx = widx0 + (int)blockIdx.z;
    __shared__ float t[32][33];
    int x = blockIdx.x * 32 + threadIdx.x;   // n
    int y = blockIdx.y * 32 + threadIdx.y;   // k
    t[threadIdx.y][threadIdx.x] = W[(size_t)y * HIDDEN + x];
    __syncthreads();
    int n = blockIdx.x * 32 + threadIdx.y;
    int k = blockIdx.y * 32 + threadIdx.x;
    g_whT[widx][(size_t)n * HIDDEN + k] = __float2half_rn(t[threadIdx.x][threadIdx.y]);
}

// ============================================================
// Fused (relu) + rmsnorm.  flags: bit0 = relu (reads `in`, writes resid),
// bit1 = write fp16 y.  Else write fp32 outf.
// ============================================================
__global__ void __launch_bounds__(256) norm_kernel(const float* __restrict__ in,
                                                   const float* __restrict__ gain,
                                                   float* __restrict__ outf,
                                                   int flags) {
    int row = blockIdx.x;
    int tid = threadIdx.x;
    const float* src = in ? in : g_resid;
    const float4* inp = reinterpret_cast<const float4*>(src + (size_t)row * HIDDEN);
    float4 v0 = inp[tid];
    float4 v1 = inp[tid + 256];

    if (flags & 1) {
        v0.x = fmaxf(v0.x, 0.f); v0.y = fmaxf(v0.y, 0.f);
        v0.z = fmaxf(v0.z, 0.f); v0.w = fmaxf(v0.w, 0.f);
        v1.x = fmaxf(v1.x, 0.f); v1.y = fmaxf(v1.y, 0.f);
        v1.z = fmaxf(v1.z, 0.f); v1.w = fmaxf(v1.w, 0.f);
        float4* rr = reinterpret_cast<float4*>(g_resid + (size_t)row * HIDDEN);
        rr[tid] = v0;
        rr[tid + 256] = v1;
    }

    float ss = v0.x * v0.x + v0.y * v0.y + v0.z * v0.z + v0.w * v0.w
             + v1.x * v1.x + v1.y * v1.y + v1.z * v1.z + v1.w * v1.w;
#pragma unroll
    for (int o = 16; o; o >>= 1) ss += __shfl_xor_sync(0xFFFFFFFFu, ss, o);
    __shared__ float red[8];
    if ((tid & 31) == 0) red[tid >> 5] = ss;
    __syncthreads();
    float tot = 0.f;
#pragma unroll
    for (int i = 0; i < 8; i++) tot += red[i];
    float scale = rsqrtf(tot * (1.0f / HIDDEN) + EPSV);

    const float4* gp = reinterpret_cast<const float4*>(gain);
    float4 gv0 = gp[tid], gv1 = gp[tid + 256];
    float4 y0, y1;
    y0.x = v0.x * scale * gv0.x; y0.y = v0.y * scale * gv0.y;
    y0.z = v0.z * scale * gv0.z; y0.w = v0.w * scale * gv0.w;
    y1.x = v1.x * scale * gv1.x; y1.y = v1.y * scale * gv1.y;
    y1.z = v1.z * scale * gv1.z; y1.w = v1.w * scale * gv1.w;

    if (flags & 2) {
        __half2 h0 = __floats2half2_rn(y0.x, y0.y);
        __half2 h1 = __floats2half2_rn(y0.z, y0.w);
        __half2 h2 = __floats2half2_rn(y1.x, y1.y);
        __half2 h3 = __floats2half2_rn(y1.z, y1.w);
        uint2* hp = reinterpret_cast<uint2*>(g_y + (size_t)row * HIDDEN);
        uint2 p0, p1;
        p0.x = *reinterpret_cast<uint32_t*>(&h0);
        p0.y = *reinterpret_cast<uint32_t*>(&h1);
        p1.x = *reinterpret_cast<uint32_t*>(&h2);
        p1.y = *reinterpret_cast<uint32_t*>(&h3);
        hp[tid] = p0; hp[tid + 256] = p1;
    } else {
        float4* op = reinterpret_cast<float4*>(outf + (size_t)row * HIDDEN);
        op[tid] = y0;
        op[tid + 256] = y1;
    }
}

// ============================================================
// Loader: one K chunk (A + B) into SW128 SMEM stage. 256 threads.
// ============================================================
__device__ __forceinline__ void load_chunk(uint32_t sbase, int m0, int n0, int k0,
                                           const char* Bg, int tid) {
    const char* Ag = reinterpret_cast<const char*>(g_y);
    // A: 128 rows x 8 x 16B = 1024 transfers
#pragma unroll
    for (int i = tid; i < 1024; i += NTHREADS) {
        int r = i >> 3; int cb = (i & 7) * 16;
        uint32_t dst = sbase + SW128(r * 128 + cb);
        const char* src = Ag + ((size_t)(m0 + r) * HIDDEN + k0) * 2 + cb;
        CP_ASYNC16(dst, src);
    }
    // B: 256 rows x 8 x 16B = 2048 transfers
#pragma unroll
    for (int i = tid; i < 2048; i += NTHREADS) {
        int r = i >> 3; int cb = (i & 7) * 16;
        uint32_t dst = sbase + ST_A + SW128(r * 128 + cb);
        const char* src = Bg + ((size_t)(n0 + r) * HIDDEN + k0) * 2 + cb;
        CP_ASYNC16(dst, src);
    }
}

// ============================================================
// GEMM: resid[m,n] += sum_k y[m,k] * W[k,n]  (single-pass fp16)
// 8 warps (2m x 4n), warp tile 64x64, 4-stage cp.async pipeline,
// k32-wide B loads (ldsm_x4), MMA pairs back-to-back.
// ============================================================
__global__ void __launch_bounds__(NTHREADS, 1) __cluster_dims__(1, 1, 1)
gemm_kernel(int widx) {
    extern __shared__ char smem[];
    uint32_t sb = smem_u32(smem);
    int tid = threadIdx.x, wid = tid >> 5, lid = tid & 31;
    int n0 = blockIdx.x * TN;
    int m0 = blockIdx.y * TM;
    const char* Bg = reinterpret_cast<const char*>(g_whT[widx]);

    uint32_t stage_base[NSTAGE];
#pragma unroll
    for (int s = 0; s < NSTAGE; s++) stage_base[s] = sb + SMEM_TILES + s * STAGE_BYTES;

    int wm = wid & 1;
    int wn = wid >> 1;
    int wm0 = wm * 64;
    int wn0 = wn * 64;

    float acc[4][8][4];
#pragma unroll
    for (int i = 0; i < 4; i++)
#pragma unroll
        for (int j = 0; j < 8; j++)
#pragma unroll
            for (int q = 0; q < 4; q++) acc[i][j][q] = 0.f;

    // prologue: fill NSTAGE-1 stages
#pragma unroll
    for (int c = 0; c < NSTAGE - 1; ++c) {
        load_chunk(stage_base[c], m0, n0, c * TK, Bg, tid);
        CP_COMMIT();
    }

    for (int c = 0; c < KCH; ++c) {
        int s = c & (NSTAGE - 1);
        if (c + NSTAGE - 1 < KCH) {
            load_chunk(stage_base[(c + NSTAGE - 1) & (NSTAGE - 1)], m0, n0,
                       (c + NSTAGE - 1) * TK, Bg, tid);
            CP_COMMIT();
            CP_WAIT3();
        } else {
            int rem = KCH - 1 - c;       // groups that must stay pending
            if (rem >= 3)      CP_WAIT3();
            else if (rem == 2) CP_WAIT2();
            else if (rem == 1) CP_WAIT1();
            else               CP_WAIT0();
        }
        __syncthreads();

        uint32_t aBase = stage_base[s];
        uint32_t bBase = stage_base[s] + ST_A;

        // Two double-k-steps per chunk; each covers k32.
#pragma unroll
        for (int kk = 0; kk < 2; ++kk) {
            int kbyte = kk * 64;   // 32 fp16 per double-step

            uint32_t a0[4][4], a1[4][4];
#pragma unroll
            for (int mt = 0; mt < 4; ++mt) {
                int r = wm0 + mt * 16 + (lid & 15);
                int cb = (lid >> 4) << 4;
                uint32_t off0 = SW128(r * 128 + kbyte + cb);
                uint32_t off1 = SW128(r * 128 + kbyte + 32 + cb);
                ldsm_x4(aBase + off0, a0[mt][0], a0[mt][1], a0[mt][2], a0[mt][3]);
                ldsm_x4(aBase + off1, a1[mt][0], a1[mt][1], a1[mt][2], a1[mt][3]);
            }

#pragma unroll
            for (int nt = 0; nt < 8; ++nt) {
                int r = wn0 + nt * 8 + (lid & 7);
                int cb = (lid >> 3) << 4;        // 0,16,32,48: k16 quarters
                uint32_t off = SW128(r * 128 + kbyte + cb);
                uint32_t b0, b1, b2, b3;
                ldsm_x4(bBase + off, b0, b1, b2, b3);
#pragma unroll
                for (int mt = 0; mt < 4; ++mt) {
                    mma16816(acc[mt][nt][0], acc[mt][nt][1], acc[mt][nt][2], acc[mt][nt][3],
                             a0[mt][0], a0[mt][1], a0[mt][2], a0[mt][3], b0, b1);
                    mma16816(acc[mt][nt][0], acc[mt][nt][1], acc[mt][nt][2], acc[mt][nt][3],
                             a1[mt][0], a1[mt][1], a1[mt][2], a1[mt][3], b2, b3);
                }
            }
        }
        __syncthreads();   // all reads of stage s done before it is refilled
    }

    // epilogue: resid += acc
    {
        int qrow = lid >> 2;
        int qcol = (lid & 3) * 2;
#pragma unroll
        for (int mt = 0; mt < 4; ++mt) {
#pragma unroll
            for (int nt = 0; nt < 8; ++nt) {
                int grow = m0 + wm0 + mt * 16 + qrow;
                int gcol = n0 + wn0 + nt * 8 + qcol;
                float* p0 = g_resid + (size_t)grow * HIDDEN + gcol;
                float2 v0 = *reinterpret_cast<float2*>(p0);
                v0.x += acc[mt][nt][0]; v0.y += acc[mt][nt][1];
                *reinterpret_cast<float2*>(p0) = v0;
                float* p1 = g_resid + (size_t)(grow + 8) * HIDDEN + gcol;
                float2 v1 = *reinterpret_cast<float2*>(p1);
                v1.x += acc[mt][nt][2]; v1.y += acc[mt][nt][3];
                *reinterpret_cast<float2*>(p1) = v1;
            }
        }
    }
}

// ============================================================
// kernel_launch
// Launch order: prep, prep, norm, gemm0, norm, gemm1, ... -> ncu "-s 5"
// captures gemm1.
// ============================================================
extern "C" void kernel_launch(void* const* d_in, const int* in_sizes, int n_in,
                              void* d_out, int out_size) {
    const float* x  = (const float*)d_in[0];
    const float* g0 = (const float*)d_in[1];
    const float* g1 = (const float*)d_in[2];
    const float* g2 = (const float*)d_in[3];
    const float* g3 = (const float*)d_in[4];
    const float* W[3] = { (const float*)d_in[5], (const float*)d_in[6], (const float*)d_in[7] };
    const float* gains[3] = { g1, g2, g3 };
    float* out = (float*)d_out;

    cudaFuncSetAttribute(gemm_kernel, cudaFuncAttributeMaxDynamicSharedMemorySize, SMEM_TOTAL);

    dim3 pb(32, 32);
    prep_w<<<dim3(HIDDEN / 32, HIDDEN / 32, 1), pb>>>(W[0], W[0], 0);
    prep_w<<<dim3(HIDDEN / 32, HIDDEN / 32, 2), pb>>>(W[1], W[2], 1);

    norm_kernel<<<TOKENS, 256>>>(x, g0, nullptr, /*relu + fp16 y*/ 3);

    dim3 gg(HIDDEN / TN, TOKENS / TM);  // (8, 256)
    for (int s = 0; s < 3; s++) {
        gemm_kernel<<<gg, 256, SMEM_TOTAL>>>(s);
        if (s < 2) {
            norm_kernel<<<TOKENS, 256>>>(nullptr, gains[s], nullptr, /*fp16 y*/ 2);
        } else {
            norm_kernel<<<TOKENS, 256>>>(nullptr, gains[s], out, /*fp32 out*/ 0);
        }
    }
}

// round 16
// speedup vs baseline: 1.7330x; 1.1279x over previous
#include <cuda_runtime.h>
#include <cuda_fp16.h>
#include <cstdint>
#include <cstddef>

// ============================================================
// Problem constants
// ============================================================
#define TOKENS 32768
#define HIDDEN 2048
#define EPSV   1e-6f

// GEMM tiling
constexpr int TM  = 128;            // CTA M tile
constexpr int TN  = 256;            // CTA N tile
constexpr int TK  = 64;             // K chunk (fp16 -> 128 bytes/row = SW128 atom)
constexpr int KCH = HIDDEN / TK;    // 32 chunks
constexpr int NTHREADS = 512;       // 16 warps: 2(m) x 8(n), warp tile 64x32

constexpr int ST_A = TM * 128;          // 16384 B (A fp16)
constexpr int ST_B = TN * 128;          // 32768 B (B fp16)
constexpr int STAGE_BYTES = ST_A + ST_B;           // 49152
constexpr int NSTAGE = 4;
constexpr int SMEM_TILES  = 1024;
constexpr int SMEM_TOTAL  = SMEM_TILES + NSTAGE * STAGE_BYTES;  // 197632 -> 1 CTA/SM

// ============================================================
// Device scratch (no allocation allowed)
// ============================================================
__device__ float   g_resid[(size_t)TOKENS * HIDDEN];
__device__ __half  g_y    [(size_t)TOKENS * HIDDEN];          // rmsnorm output, fp16
__device__ __half  g_whT  [3][(size_t)HIDDEN * HIDDEN];       // W^T fp16

// ============================================================
// Helpers
// ============================================================
__device__ __forceinline__ uint32_t smem_u32(const void* p) {
    uint32_t a;
    asm("{ .reg .u64 t; cvta.to.shared.u64 t, %1; cvt.u32.u64 %0, t; }" : "=r"(a) : "l"(p));
    return a;
}

#define SW128(o) ((o) ^ (((o) >> 3) & 0x70))

#define CP_ASYNC16(dst, src) \
    asm volatile("cp.async.cg.shared.global [%0], [%1], 16;\n" :: "r"(dst), "l"(src))
#define CP_COMMIT() asm volatile("cp.async.commit_group;\n" ::: "memory")
#define CP_WAIT3()  asm volatile("cp.async.wait_group 3;\n" ::: "memory")
#define CP_WAIT2()  asm volatile("cp.async.wait_group 2;\n" ::: "memory")
#define CP_WAIT1()  asm volatile("cp.async.wait_group 1;\n" ::: "memory")
#define CP_WAIT0()  asm volatile("cp.async.wait_group 0;\n" ::: "memory")

__device__ __forceinline__ void ldsm_x4(uint32_t addr, uint32_t& r0, uint32_t& r1,
                                        uint32_t& r2, uint32_t& r3) {
    asm volatile("ldmatrix.sync.aligned.m8n8.x4.shared.b16 {%0,%1,%2,%3}, [%4];"
        : "=r"(r0), "=r"(r1), "=r"(r2), "=r"(r3) : "r"(addr));
}
__device__ __forceinline__ void ldsm_x2(uint32_t addr, uint32_t& r0, uint32_t& r1) {
    asm volatile("ldmatrix.sync.aligned.m8n8.x2.shared.b16 {%0,%1}, [%2];"
        : "=r"(r0), "=r"(r1) : "r"(addr));
}
__device__ __forceinline__ void mma16816(float& d0, float& d1, float& d2, float& d3,
                                         uint32_t a0, uint32_t a1, uint32_t a2, uint32_t a3,
                                         uint32_t b0, uint32_t b1) {
    asm volatile(
        "mma.sync.aligned.m16n8k16.row.col.f32.f16.f16.f32 "
        "{%0,%1,%2,%3}, {%4,%5,%6,%7}, {%8,%9}, {%0,%1,%2,%3};"
        : "+f"(d0), "+f"(d1), "+f"(d2), "+f"(d3)
        : "r"(a0), "r"(a1), "r"(a2), "r"(a3), "r"(b0), "r"(b1));
}

// ============================================================
// Weight prep: transpose + fp16 round.  W[k][n] -> WT[n][k]
// Two launches total (blockIdx.z picks the pointer) so ncu's skip-index
// (-s 5) lands on the second gemm launch.
// ============================================================
__global__ void prep_w(const float* __restrict__ Wa, const float* __restrict__ Wb,
                       int widx0) {
    const float* W = (blockIdx.z == 0) ? Wa : Wb;
    int widx = widx0 + (int)blockIdx.z;
    __shared__ float t[32][33];
    int x = blockIdx.x * 32 + threadIdx.x;   // n
    int y = blockIdx.y * 32 + threadIdx.y;   // k
    t[threadIdx.y][threadIdx.x] = W[(size_t)y * HIDDEN + x];
    __syncthreads();
    int n = blockIdx.x * 32 + threadIdx.y;
    int k = blockIdx.y * 32 + threadIdx.x;
    g_whT[widx][(size_t)n * HIDDEN + k] = __float2half_rn(t[threadIdx.x][threadIdx.y]);
}

// ============================================================
// Fused (relu) + rmsnorm.  flags: bit0 = relu (reads `in`, writes resid),
// bit1 = write fp16 y.  Else write fp32 outf.
// ============================================================
__global__ void __launch_bounds__(256) norm_kernel(const float* __restrict__ in,
                                                   const float* __restrict__ gain,
                                                   float* __restrict__ outf,
                                                   int flags) {
    int row = blockIdx.x;
    int tid = threadIdx.x;
    const float* src = in ? in : g_resid;
    const float4* inp = reinterpret_cast<const float4*>(src + (size_t)row * HIDDEN);
    float4 v0 = inp[tid];
    float4 v1 = inp[tid + 256];

    if (flags & 1) {
        v0.x = fmaxf(v0.x, 0.f); v0.y = fmaxf(v0.y, 0.f);
        v0.z = fmaxf(v0.z, 0.f); v0.w = fmaxf(v0.w, 0.f);
        v1.x = fmaxf(v1.x, 0.f); v1.y = fmaxf(v1.y, 0.f);
        v1.z = fmaxf(v1.z, 0.f); v1.w = fmaxf(v1.w, 0.f);
        float4* rr = reinterpret_cast<float4*>(g_resid + (size_t)row * HIDDEN);
        rr[tid] = v0;
        rr[tid + 256] = v1;
    }

    float ss = v0.x * v0.x + v0.y * v0.y + v0.z * v0.z + v0.w * v0.w
             + v1.x * v1.x + v1.y * v1.y + v1.z * v1.z + v1.w * v1.w;
#pragma unroll
    for (int o = 16; o; o >>= 1) ss += __shfl_xor_sync(0xFFFFFFFFu, ss, o);
    __shared__ float red[8];
    if ((tid & 31) == 0) red[tid >> 5] = ss;
    __syncthreads();
    float tot = 0.f;
#pragma unroll
    for (int i = 0; i < 8; i++) tot += red[i];
    float scale = rsqrtf(tot * (1.0f / HIDDEN) + EPSV);

    const float4* gp = reinterpret_cast<const float4*>(gain);
    float4 gv0 = gp[tid], gv1 = gp[tid + 256];
    float4 y0, y1;
    y0.x = v0.x * scale * gv0.x; y0.y = v0.y * scale * gv0.y;
    y0.z = v0.z * scale * gv0.z; y0.w = v0.w * scale * gv0.w;
    y1.x = v1.x * scale * gv1.x; y1.y = v1.y * scale * gv1.y;
    y1.z = v1.z * scale * gv1.z; y1.w = v1.w * scale * gv1.w;

    if (flags & 2) {
        __half2 h0 = __floats2half2_rn(y0.x, y0.y);
        __half2 h1 = __floats2half2_rn(y0.z, y0.w);
        __half2 h2 = __floats2half2_rn(y1.x, y1.y);
        __half2 h3 = __floats2half2_rn(y1.z, y1.w);
        uint2* hp = reinterpret_cast<uint2*>(g_y + (size_t)row * HIDDEN);
        uint2 p0, p1;
        p0.x = *reinterpret_cast<uint32_t*>(&h0);
        p0.y = *reinterpret_cast<uint32_t*>(&h1);
        p1.x = *reinterpret_cast<uint32_t*>(&h2);
        p1.y = *reinterpret_cast<uint32_t*>(&h3);
        hp[tid] = p0; hp[tid + 256] = p1;
    } else {
        float4* op = reinterpret_cast<float4*>(outf + (size_t)row * HIDDEN);
        op[tid] = y0;
        op[tid + 256] = y1;
    }
}

// ============================================================
// Loader: one K chunk (A + B) into SW128 SMEM stage. 512 threads.
// ============================================================
__device__ __forceinline__ void load_chunk(uint32_t sbase, int m0, int n0, int k0,
                                           const char* Bg, int tid) {
    const char* Ag = reinterpret_cast<const char*>(g_y);
    // A: 128 rows x 8 x 16B = 1024 transfers
#pragma unroll
    for (int i = tid; i < 1024; i += NTHREADS) {
        int r = i >> 3; int cb = (i & 7) * 16;
        uint32_t dst = sbase + SW128(r * 128 + cb);
        const char* src = Ag + ((size_t)(m0 + r) * HIDDEN + k0) * 2 + cb;
        CP_ASYNC16(dst, src);
    }
    // B: 256 rows x 8 x 16B = 2048 transfers
#pragma unroll
    for (int i = tid; i < 2048; i += NTHREADS) {
        int r = i >> 3; int cb = (i & 7) * 16;
        uint32_t dst = sbase + ST_A + SW128(r * 128 + cb);
        const char* src = Bg + ((size_t)(n0 + r) * HIDDEN + k0) * 2 + cb;
        CP_ASYNC16(dst, src);
    }
}

// ============================================================
// GEMM: resid[m,n] += sum_k y[m,k] * W[k,n]  (single-pass fp16)
// 16 warps (2m x 8n), warp tile 64x32 -> acc 64 regs/thread (no RF cap),
// occ 25% (16 warps/SM).  4-stage cp.async pipeline.
// ============================================================
__global__ void __launch_bounds__(NTHREADS, 1) __cluster_dims__(1, 1, 1)
gemm_kernel(int widx) {
    extern __shared__ char smem[];
    uint32_t sb = smem_u32(smem);
    int tid = threadIdx.x, wid = tid >> 5, lid = tid & 31;
    int n0 = blockIdx.x * TN;
    int m0 = blockIdx.y * TM;
    const char* Bg = reinterpret_cast<const char*>(g_whT[widx]);

    uint32_t stage_base[NSTAGE];
#pragma unroll
    for (int s = 0; s < NSTAGE; s++) stage_base[s] = sb + SMEM_TILES + s * STAGE_BYTES;

    int wm = wid & 1;          // 0..1
    int wn = wid >> 1;         // 0..7
    int wm0 = wm * 64;
    int wn0 = wn * 32;

    float acc[4][4][4];        // [m16 tile][n8 tile][frag] = 64 regs
#pragma unroll
    for (int i = 0; i < 4; i++)
#pragma unroll
        for (int j = 0; j < 4; j++)
#pragma unroll
            for (int q = 0; q < 4; q++) acc[i][j][q] = 0.f;

    // prologue: fill NSTAGE-1 stages
#pragma unroll
    for (int c = 0; c < NSTAGE - 1; ++c) {
        load_chunk(stage_base[c], m0, n0, c * TK, Bg, tid);
        CP_COMMIT();
    }

    for (int c = 0; c < KCH; ++c) {
        int s = c & (NSTAGE - 1);
        if (c + NSTAGE - 1 < KCH) {
            load_chunk(stage_base[(c + NSTAGE - 1) & (NSTAGE - 1)], m0, n0,
                       (c + NSTAGE - 1) * TK, Bg, tid);
            CP_COMMIT();
            CP_WAIT3();
        } else {
            int rem = KCH - 1 - c;
            if (rem >= 3)      CP_WAIT3();
            else if (rem == 2) CP_WAIT2();
            else if (rem == 1) CP_WAIT1();
            else               CP_WAIT0();
        }
        __syncthreads();

        uint32_t aBase = stage_base[s];
        uint32_t bBase = stage_base[s] + ST_A;

#pragma unroll
        for (int ks = 0; ks < 4; ++ks) {
            int kbyte = ks * 32;   // 16 fp16 per k-step

            uint32_t ah[4][4];
#pragma unroll
            for (int mt = 0; mt < 4; ++mt) {
                int r = wm0 + mt * 16 + (lid & 15);
                int cb = kbyte + ((lid >> 4) << 4);
                uint32_t off = SW128(r * 128 + cb);
                ldsm_x4(aBase + off, ah[mt][0], ah[mt][1], ah[mt][2], ah[mt][3]);
            }
            uint32_t bf[4][2];
#pragma unroll
            for (int nt = 0; nt < 4; ++nt) {
                int r = wn0 + nt * 8 + (lid & 7);
                int cb = kbyte + (((lid >> 3) & 1) << 4);
                uint32_t off = SW128(r * 128 + cb);
                ldsm_x2(bBase + off, bf[nt][0], bf[nt][1]);
            }
#pragma unroll
            for (int nt = 0; nt < 4; ++nt) {
#pragma unroll
                for (int mt = 0; mt < 4; ++mt) {
                    mma16816(acc[mt][nt][0], acc[mt][nt][1], acc[mt][nt][2], acc[mt][nt][3],
                             ah[mt][0], ah[mt][1], ah[mt][2], ah[mt][3],
                             bf[nt][0], bf[nt][1]);
                }
            }
        }
        __syncthreads();   // all reads of stage s done before it is refilled
    }

    // epilogue: resid += acc
    {
        int qrow = lid >> 2;
        int qcol = (lid & 3) * 2;
#pragma unroll
        for (int mt = 0; mt < 4; ++mt) {
#pragma unroll
            for (int nt = 0; nt < 4; ++nt) {
                int grow = m0 + wm0 + mt * 16 + qrow;
                int gcol = n0 + wn0 + nt * 8 + qcol;
                float* p0 = g_resid + (size_t)grow * HIDDEN + gcol;
                float2 v0 = *reinterpret_cast<float2*>(p0);
                v0.x += acc[mt][nt][0]; v0.y += acc[mt][nt][1];
                *reinterpret_cast<float2*>(p0) = v0;
                float* p1 = g_resid + (size_t)(grow + 8) * HIDDEN + gcol;
                float2 v1 = *reinterpret_cast<float2*>(p1);
                v1.x += acc[mt][nt][2]; v1.y += acc[mt][nt][3];
                *reinterpret_cast<float2*>(p1) = v1;
            }
        }
    }
}

// ============================================================
// kernel_launch
// Launch order: prep, prep, norm, gemm0, norm, gemm1, ... -> ncu "-s 5"
// captures gemm1.
// ============================================================
extern "C" void kernel_launch(void* const* d_in, const int* in_sizes, int n_in,
                              void* d_out, int out_size) {
    const float* x  = (const float*)d_in[0];
    const float* g0 = (const float*)d_in[1];
    const float* g1 = (const float*)d_in[2];
    const float* g2 = (const float*)d_in[3];
    const float* g3 = (const float*)d_in[4];
    const float* W[3] = { (const float*)d_in[5], (const float*)d_in[6], (const float*)d_in[7] };
    const float* gains[3] = { g1, g2, g3 };
    float* out = (float*)d_out;

    cudaFuncSetAttribute(gemm_kernel, cudaFuncAttributeMaxDynamicSharedMemorySize, SMEM_TOTAL);

    dim3 pb(32, 32);
    prep_w<<<dim3(HIDDEN / 32, HIDDEN / 32, 1), pb>>>(W[0], W[0], 0);
    prep_w<<<dim3(HIDDEN / 32, HIDDEN / 32, 2), pb>>>(W[1], W[2], 1);

    norm_kernel<<<TOKENS, 256>>>(x, g0, nullptr, /*relu + fp16 y*/ 3);

    dim3 gg(HIDDEN / TN, TOKENS / TM);  // (8, 256)
    for (int s = 0; s < 3; s++) {
        gemm_kernel<<<gg, NTHREADS, SMEM_TOTAL>>>(s);
        if (s < 2) {
            norm_kernel<<<TOKENS, 256>>>(nullptr, gains[s], nullptr, /*fp16 y*/ 2);
        } else {
            norm_kernel<<<TOKENS, 256>>>(nullptr, gains[s], out, /*fp32 out*/ 0);
        }
    }
}

// round 17
// speedup vs baseline: 1.8287x; 1.0552x over previous
#include <cuda_runtime.h>
#include <cuda_fp16.h>
#include <cstdint>
#include <cstddef>

// ============================================================
// Problem constants
// ============================================================
#define TOKENS 32768
#define HIDDEN 2048
#define EPSV   1e-6f

// GEMM tiling
constexpr int TM  = 128;            // CTA M tile
constexpr int TN  = 256;            // CTA N tile
constexpr int TK  = 64;             // K chunk (fp16 -> 128 bytes/row = SW128 atom)
constexpr int KCH = HIDDEN / TK;    // 32 chunks
constexpr int NTHREADS = 512;       // 16 warps: 2(m) x 8(n), warp tile 64x32

constexpr int ST_A = TM * 128;          // 16384 B (A fp16)
constexpr int ST_B = TN * 128;          // 32768 B (B fp16)
constexpr int STAGE_BYTES = ST_A + ST_B;           // 49152
constexpr int NSTAGE = 4;
constexpr int SMEM_TILES  = 1024;
constexpr int SMEM_TOTAL  = SMEM_TILES + NSTAGE * STAGE_BYTES;  // 197632 -> 1 CTA/SM

// ============================================================
// Device scratch (no allocation allowed)
// ============================================================
__device__ float   g_resid[(size_t)TOKENS * HIDDEN];
__device__ __half  g_y    [(size_t)TOKENS * HIDDEN];          // rmsnorm output, fp16
__device__ __half  g_whT  [3][(size_t)HIDDEN * HIDDEN];       // W^T fp16

// ============================================================
// Helpers
// ============================================================
__device__ __forceinline__ uint32_t smem_u32(const void* p) {
    uint32_t a;
    asm("{ .reg .u64 t; cvta.to.shared.u64 t, %1; cvt.u32.u64 %0, t; }" : "=r"(a) : "l"(p));
    return a;
}

#define SW128(o) ((o) ^ (((o) >> 3) & 0x70))

#define CP_ASYNC16(dst, src) \
    asm volatile("cp.async.cg.shared.global [%0], [%1], 16;\n" :: "r"(dst), "l"(src))
#define CP_COMMIT() asm volatile("cp.async.commit_group;\n" ::: "memory")
#define CP_WAIT2()  asm volatile("cp.async.wait_group 2;\n" ::: "memory")
#define CP_WAIT1()  asm volatile("cp.async.wait_group 1;\n" ::: "memory")
#define CP_WAIT0()  asm volatile("cp.async.wait_group 0;\n" ::: "memory")

__device__ __forceinline__ void ldsm_x4(uint32_t addr, uint32_t& r0, uint32_t& r1,
                                        uint32_t& r2, uint32_t& r3) {
    asm volatile("ldmatrix.sync.aligned.m8n8.x4.shared.b16 {%0,%1,%2,%3}, [%4];"
        : "=r"(r0), "=r"(r1), "=r"(r2), "=r"(r3) : "r"(addr));
}
__device__ __forceinline__ void ldsm_x2(uint32_t addr, uint32_t& r0, uint32_t& r1) {
    asm volatile("ldmatrix.sync.aligned.m8n8.x2.shared.b16 {%0,%1}, [%2];"
        : "=r"(r0), "=r"(r1) : "r"(addr));
}
__device__ __forceinline__ void mma16816(float& d0, float& d1, float& d2, float& d3,
                                         uint32_t a0, uint32_t a1, uint32_t a2, uint32_t a3,
                                         uint32_t b0, uint32_t b1) {
    asm volatile(
        "mma.sync.aligned.m16n8k16.row.col.f32.f16.f16.f32 "
        "{%0,%1,%2,%3}, {%4,%5,%6,%7}, {%8,%9}, {%0,%1,%2,%3};"
        : "+f"(d0), "+f"(d1), "+f"(d2), "+f"(d3)
        : "r"(a0), "r"(a1), "r"(a2), "r"(a3), "r"(b0), "r"(b1));
}

// ============================================================
// Weight prep: transpose + fp16 round.  W[k][n] -> WT[n][k]
// Two launches total (blockIdx.z picks the pointer) so ncu's skip-index
// (-s 5) lands on the second gemm launch.
// ============================================================
__global__ void prep_w(const float* __restrict__ Wa, const float* __restrict__ Wb,
                       int widx0) {
    const float* W = (blockIdx.z == 0) ? Wa : Wb;
    int widx = widx0 + (int)blockIdx.z;
    __shared__ float t[32][33];
    int x = blockIdx.x * 32 + threadIdx.x;   // n
    int y = blockIdx.y * 32 + threadIdx.y;   // k
    t[threadIdx.y][threadIdx.x] = W[(size_t)y * HIDDEN + x];
    __syncthreads();
    int n = blockIdx.x * 32 + threadIdx.y;
    int k = blockIdx.y * 32 + threadIdx.x;
    g_whT[widx][(size_t)n * HIDDEN + k] = __float2half_rn(t[threadIdx.x][threadIdx.y]);
}

// ============================================================
// Fused (relu) + rmsnorm.  flags: bit0 = relu (reads `in`, writes resid),
// bit1 = write fp16 y.  Else write fp32 outf.
// ============================================================
__global__ void __launch_bounds__(256) norm_kernel(const float* __restrict__ in,
                                                   const float* __restrict__ gain,
                                                   float* __restrict__ outf,
                                                   int flags) {
    int row = blockIdx.x;
    int tid = threadIdx.x;
    const float* src = in ? in : g_resid;
    const float4* inp = reinterpret_cast<const float4*>(src + (size_t)row * HIDDEN);
    float4 v0 = inp[tid];
    float4 v1 = inp[tid + 256];

    if (flags & 1) {
        v0.x = fmaxf(v0.x, 0.f); v0.y = fmaxf(v0.y, 0.f);
        v0.z = fmaxf(v0.z, 0.f); v0.w = fmaxf(v0.w, 0.f);
        v1.x = fmaxf(v1.x, 0.f); v1.y = fmaxf(v1.y, 0.f);
        v1.z = fmaxf(v1.z, 0.f); v1.w = fmaxf(v1.w, 0.f);
        float4* rr = reinterpret_cast<float4*>(g_resid + (size_t)row * HIDDEN);
        rr[tid] = v0;
        rr[tid + 256] = v1;
    }

    float ss = v0.x * v0.x + v0.y * v0.y + v0.z * v0.z + v0.w * v0.w
             + v1.x * v1.x + v1.y * v1.y + v1.z * v1.z + v1.w * v1.w;
#pragma unroll
    for (int o = 16; o; o >>= 1) ss += __shfl_xor_sync(0xFFFFFFFFu, ss, o);
    __shared__ float red[8];
    if ((tid & 31) == 0) red[tid >> 5] = ss;
    __syncthreads();
    float tot = 0.f;
#pragma unroll
    for (int i = 0; i < 8; i++) tot += red[i];
    float scale = rsqrtf(tot * (1.0f / HIDDEN) + EPSV);

    const float4* gp = reinterpret_cast<const float4*>(gain);
    float4 gv0 = gp[tid], gv1 = gp[tid + 256];
    float4 y0, y1;
    y0.x = v0.x * scale * gv0.x; y0.y = v0.y * scale * gv0.y;
    y0.z = v0.z * scale * gv0.z; y0.w = v0.w * scale * gv0.w;
    y1.x = v1.x * scale * gv1.x; y1.y = v1.y * scale * gv1.y;
    y1.z = v1.z * scale * gv1.z; y1.w = v1.w * scale * gv1.w;

    if (flags & 2) {
        __half2 h0 = __floats2half2_rn(y0.x, y0.y);
        __half2 h1 = __floats2half2_rn(y0.z, y0.w);
        __half2 h2 = __floats2half2_rn(y1.x, y1.y);
        __half2 h3 = __floats2half2_rn(y1.z, y1.w);
        uint2* hp = reinterpret_cast<uint2*>(g_y + (size_t)row * HIDDEN);
        uint2 p0, p1;
        p0.x = *reinterpret_cast<uint32_t*>(&h0);
        p0.y = *reinterpret_cast<uint32_t*>(&h1);
        p1.x = *reinterpret_cast<uint32_t*>(&h2);
        p1.y = *reinterpret_cast<uint32_t*>(&h3);
        hp[tid] = p0; hp[tid + 256] = p1;
    } else {
        float4* op = reinterpret_cast<float4*>(outf + (size_t)row * HIDDEN);
        op[tid] = y0;
        op[tid + 256] = y1;
    }
}

// ============================================================
// Loader: one K chunk (A + B) into SW128 SMEM stage. 512 threads.
// ============================================================
__device__ __forceinline__ void load_chunk(uint32_t sbase, int m0, int n0, int k0,
                                           const char* Bg, int tid) {
    const char* Ag = reinterpret_cast<const char*>(g_y);
    // A: 128 rows x 8 x 16B = 1024 transfers
#pragma unroll
    for (int i = tid; i < 1024; i += NTHREADS) {
        int r = i >> 3; int cb = (i & 7) * 16;
        uint32_t dst = sbase + SW128(r * 128 + cb);
        const char* src = Ag + ((size_t)(m0 + r) * HIDDEN + k0) * 2 + cb;
        CP_ASYNC16(dst, src);
    }
    // B: 256 rows x 8 x 16B = 2048 transfers
#pragma unroll
    for (int i = tid; i < 2048; i += NTHREADS) {
        int r = i >> 3; int cb = (i & 7) * 16;
        uint32_t dst = sbase + ST_A + SW128(r * 128 + cb);
        const char* src = Bg + ((size_t)(n0 + r) * HIDDEN + k0) * 2 + cb;
        CP_ASYNC16(dst, src);
    }
}

// ============================================================
// GEMM: resid[m,n] += sum_k y[m,k] * W[k,n]  (single-pass fp16)
// 16 warps (2m x 8n), warp tile 64x32, 4-stage cp.async pipeline with
// prefetch depth 2 -> ONE __syncthreads per chunk (stage (c+2)&3 can never
// collide with stage (c-1)&3 still being read).
// ============================================================
__global__ void __launch_bounds__(NTHREADS, 1) __cluster_dims__(1, 1, 1)
gemm_kernel(int widx) {
    extern __shared__ char smem[];
    uint32_t sb = smem_u32(smem);
    int tid = threadIdx.x, wid = tid >> 5, lid = tid & 31;
    int n0 = blockIdx.x * TN;
    int m0 = blockIdx.y * TM;
    const char* Bg = reinterpret_cast<const char*>(g_whT[widx]);

    uint32_t stage_base[NSTAGE];
#pragma unroll
    for (int s = 0; s < NSTAGE; s++) stage_base[s] = sb + SMEM_TILES + s * STAGE_BYTES;

    int wm = wid & 1;          // 0..1
    int wn = wid >> 1;         // 0..7
    int wm0 = wm * 64;
    int wn0 = wn * 32;

    float acc[4][4][4];        // [m16 tile][n8 tile][frag] = 64 regs
#pragma unroll
    for (int i = 0; i < 4; i++)
#pragma unroll
        for (int j = 0; j < 4; j++)
#pragma unroll
            for (int q = 0; q < 4; q++) acc[i][j][q] = 0.f;

    // prologue: prefetch depth 2
    load_chunk(stage_base[0], m0, n0, 0, Bg, tid);
    CP_COMMIT();
    load_chunk(stage_base[1], m0, n0, TK, Bg, tid);
    CP_COMMIT();

    for (int c = 0; c < KCH; ++c) {
        int s = c & (NSTAGE - 1);
        if (c + 2 < KCH) {
            load_chunk(stage_base[(c + 2) & (NSTAGE - 1)], m0, n0, (c + 2) * TK, Bg, tid);
            CP_COMMIT();
            CP_WAIT2();             // stage c complete (pending: c+1, c+2)
        } else if (c + 1 < KCH) {
            CP_WAIT1();             // pending: c+1
        } else {
            CP_WAIT0();
        }
        __syncthreads();            // single barrier per chunk

        uint32_t aBase = stage_base[s];
        uint32_t bBase = stage_base[s] + ST_A;

#pragma unroll
        for (int ks = 0; ks < 4; ++ks) {
            int kbyte = ks * 32;   // 16 fp16 per k-step

            uint32_t ah[4][4];
#pragma unroll
            for (int mt = 0; mt < 4; ++mt) {
                int r = wm0 + mt * 16 + (lid & 15);
                int cb = kbyte + ((lid >> 4) << 4);
                uint32_t off = SW128(r * 128 + cb);
                ldsm_x4(aBase + off, ah[mt][0], ah[mt][1], ah[mt][2], ah[mt][3]);
            }
            uint32_t bf[4][2];
#pragma unroll
            for (int nt = 0; nt < 4; ++nt) {
                int r = wn0 + nt * 8 + (lid & 7);
                int cb = kbyte + (((lid >> 3) & 1) << 4);
                uint32_t off = SW128(r * 128 + cb);
                ldsm_x2(bBase + off, bf[nt][0], bf[nt][1]);
            }
#pragma unroll
            for (int nt = 0; nt < 4; ++nt) {
#pragma unroll
                for (int mt = 0; mt < 4; ++mt) {
                    mma16816(acc[mt][nt][0], acc[mt][nt][1], acc[mt][nt][2], acc[mt][nt][3],
                             ah[mt][0], ah[mt][1], ah[mt][2], ah[mt][3],
                             bf[nt][0], bf[nt][1]);
                }
            }
        }
        // no trailing barrier: next iteration's loads target stage (c+3)&3,
        // which no warp can still be reading (readers are at stage >= c).
    }

    // epilogue: resid += acc
    {
        int qrow = lid >> 2;
        int qcol = (lid & 3) * 2;
#pragma unroll
        for (int mt = 0; mt < 4; ++mt) {
#pragma unroll
            for (int nt = 0; nt < 4; ++nt) {
                int grow = m0 + wm0 + mt * 16 + qrow;
                int gcol = n0 + wn0 + nt * 8 + qcol;
                float* p0 = g_resid + (size_t)grow * HIDDEN + gcol;
                float2 v0 = *reinterpret_cast<float2*>(p0);
                v0.x += acc[mt][nt][0]; v0.y += acc[mt][nt][1];
                *reinterpret_cast<float2*>(p0) = v0;
                float* p1 = g_resid + (size_t)(grow + 8) * HIDDEN + gcol;
                float2 v1 = *reinterpret_cast<float2*>(p1);
                v1.x += acc[mt][nt][2]; v1.y += acc[mt][nt][3];
                *reinterpret_cast<float2*>(p1) = v1;
            }
        }
    }
}

// ============================================================
// kernel_launch
// Launch order: prep, prep, norm, gemm0, norm, gemm1, ... -> ncu "-s 5"
// captures gemm1.
// ============================================================
extern "C" void kernel_launch(void* const* d_in, const int* in_sizes, int n_in,
                              void* d_out, int out_size) {
    const float* x  = (const float*)d_in[0];
    const float* g0 = (const float*)d_in[1];
    const float* g1 = (const float*)d_in[2];
    const float* g2 = (const float*)d_in[3];
    const float* g3 = (const float*)d_in[4];
    const float* W[3] = { (const float*)d_in[5], (const float*)d_in[6], (const float*)d_in[7] };
    const float* gains[3] = { g1, g2, g3 };
    float* out = (float*)d_out;

    cudaFuncSetAttribute(gemm_kernel, cudaFuncAttributeMaxDynamicSharedMemorySize, SMEM_TOTAL);

    dim3 pb(32, 32);
    prep_w<<<dim3(HIDDEN / 32, HIDDEN / 32, 1), pb>>>(W[0], W[0], 0);
    prep_w<<<dim3(HIDDEN / 32, HIDDEN / 32, 2), pb>>>(W[1], W[2], 1);

    norm_kernel<<<TOKENS, 256>>>(x, g0, nullptr, /*relu + fp16 y*/ 3);

    dim3 gg(HIDDEN / TN, TOKENS / TM);  // (8, 256)
    for (int s = 0; s < 3; s++) {
        gemm_kernel<<<gg, NTHREADS, SMEM_TOTAL>>>(s);
        if (s < 2) {
            norm_kernel<<<TOKENS, 256>>>(nullptr, gains[s], nullptr, /*fp16 y*/ 2);
        } else {
            norm_kernel<<<TOKENS, 256>>>(nullptr, gains[s], out, /*fp32 out*/ 0);
        }
    }
}